// round 1
// baseline (speedup 1.0000x reference)
#include <cuda_runtime.h>
#include <cuda_bf16.h>
#include <cstdint>
#include <math_constants.h>

// Problem constants
#define CDIM 512
#define NHEAD 16
#define HD 32
#define LTOK 49
#define BNW 4096
#define MROWS (BNW * LTOK)          // 200704
#define NQKV (3 * CDIM)              // 1536
#define SLAB (LTOK * HD)             // 1568 floats per (window,head) per part
#define WINSTRIDE (NHEAD * SLAB)     // 25088
#define PARTSTRIDE ((size_t)CDIM * MROWS)  // 512*200704

// Scratch: qkv stored transposed: g_qkvT[col * MROWS + (b*49+l)], col in [0,1536)
__device__ float g_qkvT[(size_t)NQKV * MROWS];          // 1.233 GB
__device__ float g_attnout[(size_t)MROWS * CDIM];       // 411 MB

// ---------------------------------------------------------------------------
// SGEMM: C[M,N] = A[M,K] @ B[K,N] + bias[N]
// BM=128, BN=128, BK=8, 256 threads, 8x8 per thread.
// MODE 0: plain row-major store to C
// MODE 1: QKV scatter store: g_qkvT[col*MROWS + row]
// MODE 2: A is g_attnout (param A ignored), plain store to C
// Assumes M%128==0, N%128==0, K%8==0 (true here: 200704, 1536/512, 512).
// ---------------------------------------------------------------------------
template <int MODE>
__global__ __launch_bounds__(256) void sgemm_kernel(
    const float* __restrict__ A, const float* __restrict__ B,
    const float* __restrict__ bias, float* __restrict__ C,
    int M, int N, int K)
{
    constexpr int BM = 128, BN = 128, BK = 8, TM = 8, TN = 8;
    __shared__ float As[BK][BM];
    __shared__ float Bs[BK][BN];

    const float* Abase = (MODE == 2) ? g_attnout : A;

    int tx = threadIdx.x;
    int bn = blockIdx.x, bm = blockIdx.y;
    int tr = tx >> 4, tc = tx & 15;

    int aRow = tx >> 1;
    int aK4  = (tx & 1) * 4;
    int bRow = tx >> 5;
    int bCol = (tx & 31) * 4;

    const float* Aptr = Abase + (size_t)(bm * BM + aRow) * K + aK4;
    const float* Bptr = B + (size_t)bRow * N + bn * BN + bCol;

    float acc[TM][TN];
    #pragma unroll
    for (int i = 0; i < TM; i++)
        #pragma unroll
        for (int j = 0; j < TN; j++) acc[i][j] = 0.f;

    for (int k0 = 0; k0 < K; k0 += BK) {
        float4 a = *(const float4*)(Aptr + k0);
        float4 b = *(const float4*)(Bptr + (size_t)k0 * N);
        As[aK4 + 0][aRow] = a.x;
        As[aK4 + 1][aRow] = a.y;
        As[aK4 + 2][aRow] = a.z;
        As[aK4 + 3][aRow] = a.w;
        *(float4*)&Bs[bRow][bCol] = b;
        __syncthreads();

        #pragma unroll
        for (int kk = 0; kk < BK; kk++) {
            float ra[TM], rb[TN];
            #pragma unroll
            for (int i = 0; i < TM; i++) ra[i] = As[kk][tr * TM + i];
            #pragma unroll
            for (int j = 0; j < TN; j++) rb[j] = Bs[kk][tc * TN + j];
            #pragma unroll
            for (int i = 0; i < TM; i++)
                #pragma unroll
                for (int j = 0; j < TN; j++)
                    acc[i][j] = fmaf(ra[i], rb[j], acc[i][j]);
        }
        __syncthreads();
    }

    if (MODE == 1) {
        // scatter: dst[col * MROWS + row], rows contiguous per column
        int r0 = bm * BM + tr * TM;
        #pragma unroll
        for (int j = 0; j < TN; j++) {
            int col = bn * BN + tc * TN + j;
            float bv = bias[col];
            float* dst = g_qkvT + (size_t)col * MROWS + r0;
            float4 v0 = make_float4(acc[0][j] + bv, acc[1][j] + bv,
                                    acc[2][j] + bv, acc[3][j] + bv);
            float4 v1 = make_float4(acc[4][j] + bv, acc[5][j] + bv,
                                    acc[6][j] + bv, acc[7][j] + bv);
            *(float4*)(dst)     = v0;
            *(float4*)(dst + 4) = v1;
        }
    } else {
        int c0 = bn * BN + tc * TN;
        float4 bv0 = *(const float4*)(bias + c0);
        float4 bv1 = *(const float4*)(bias + c0 + 4);
        #pragma unroll
        for (int i = 0; i < TM; i++) {
            int row = bm * BM + tr * TM + i;
            float* dst = C + (size_t)row * N + c0;
            float4 v0 = make_float4(acc[i][0] + bv0.x, acc[i][1] + bv0.y,
                                    acc[i][2] + bv0.z, acc[i][3] + bv0.w);
            float4 v1 = make_float4(acc[i][4] + bv1.x, acc[i][5] + bv1.y,
                                    acc[i][6] + bv1.z, acc[i][7] + bv1.w);
            *(float4*)(dst)     = v0;
            *(float4*)(dst + 4) = v1;
        }
    }
}

// ---------------------------------------------------------------------------
// Attention: one block per (window b2, head h). Q/K/V slabs are contiguous
// 1568-float runs in g_qkvT. Computes S = Q@K^T + bias + mask, softmax,
// O = P@V, writes to g_attnout[(b2*49+l)*512 + h*32+d].
// ---------------------------------------------------------------------------
__global__ __launch_bounds__(256) void attn_kernel(
    const float* __restrict__ mask,
    const float* __restrict__ bias_table,
    const int*   __restrict__ index_table)
{
    __shared__ float sQ[SLAB];          // [l][d]
    __shared__ float sKT[HD * LTOK];    // [d][m] transposed
    __shared__ float sV[SLAB];          // [m][d]
    __shared__ float sS[LTOK * LTOK];   // 2401 scores

    int tid = threadIdx.x;
    int b2 = blockIdx.x >> 4;
    int h  = blockIdx.x & 15;

    size_t base = (size_t)b2 * WINSTRIDE + (size_t)h * SLAB;
    const float* Qg = g_qkvT + base;
    const float* Kg = g_qkvT + PARTSTRIDE + base;
    const float* Vg = g_qkvT + 2 * PARTSTRIDE + base;

    // Load slabs (392 float4 each). K goes in transposed.
    for (int t = tid; t < SLAB / 4; t += 256) {
        ((float4*)sQ)[t] = ((const float4*)Qg)[t];
        ((float4*)sV)[t] = ((const float4*)Vg)[t];
        float4 kv = ((const float4*)Kg)[t];
        int j  = t * 4;
        int l2 = j >> 5;
        int d  = j & 31;
        sKT[(d + 0) * LTOK + l2] = kv.x;
        sKT[(d + 1) * LTOK + l2] = kv.y;
        sKT[(d + 2) * LTOK + l2] = kv.z;
        sKT[(d + 3) * LTOK + l2] = kv.w;
    }
    __syncthreads();

    // Scores + bias + mask
    const float* mrow = mask + (size_t)(b2 & 63) * (LTOK * LTOK);
    for (int o = tid; o < LTOK * LTOK; o += 256) {
        int l = o / LTOK;
        int m = o - l * LTOK;
        float acc = 0.f;
        #pragma unroll
        for (int d = 0; d < HD; d++)
            acc = fmaf(sQ[l * HD + d], sKT[d * LTOK + m], acc);
        int idx = index_table[o];
        sS[o] = acc + bias_table[idx * NHEAD + h] + mrow[o];
    }
    __syncthreads();

    // Softmax per row (warp per row, 49 elems -> 2 per lane)
    int warp = tid >> 5, lane = tid & 31;
    for (int row = warp; row < LTOK; row += 8) {
        float* s = sS + row * LTOK;
        float e0 = s[lane];
        float e1 = (lane + 32 < LTOK) ? s[lane + 32] : -CUDART_INF_F;
        float mx = fmaxf(e0, e1);
        #pragma unroll
        for (int off = 16; off; off >>= 1)
            mx = fmaxf(mx, __shfl_xor_sync(0xffffffffu, mx, off));
        float p0 = __expf(e0 - mx);
        float p1 = (lane + 32 < LTOK) ? __expf(e1 - mx) : 0.f;
        float sum = p0 + p1;
        #pragma unroll
        for (int off = 16; off; off >>= 1)
            sum += __shfl_xor_sync(0xffffffffu, sum, off);
        float inv = 1.f / sum;
        s[lane] = p0 * inv;
        if (lane + 32 < LTOK) s[lane + 32] = p1 * inv;
    }
    __syncthreads();

    // O = P @ V, write to (B,L,C) layout
    for (int o = tid; o < SLAB; o += 256) {
        int l = o >> 5;
        int d = o & 31;
        const float* p = sS + l * LTOK;
        float acc = 0.f;
        #pragma unroll
        for (int m = 0; m < LTOK; m++)
            acc = fmaf(p[m], sV[m * HD + d], acc);
        g_attnout[((size_t)b2 * LTOK + l) * CDIM + h * HD + d] = acc;
    }
}

// ---------------------------------------------------------------------------
extern "C" void kernel_launch(void* const* d_in, const int* in_sizes, int n_in,
                              void* d_out, int out_size)
{
    const float* x          = (const float*)d_in[0];
    const float* mask       = (const float*)d_in[1];
    const float* w_qkv      = (const float*)d_in[2];
    const float* b_qkv      = (const float*)d_in[3];
    const float* w_proj     = (const float*)d_in[4];
    const float* b_proj     = (const float*)d_in[5];
    const float* bias_table = (const float*)d_in[6];
    const int*   index_table= (const int*)d_in[7];
    float* out = (float*)d_out;

    // 1) QKV GEMM with transposed scatter epilogue
    {
        dim3 grid(NQKV / 128, MROWS / 128);   // (12, 1568)
        sgemm_kernel<1><<<grid, 256>>>(x, w_qkv, b_qkv, nullptr,
                                       MROWS, NQKV, CDIM);
    }
    // 2) Fused window attention (one block per window*head)
    {
        attn_kernel<<<BNW * NHEAD, 256>>>(mask, bias_table, index_table);
    }
    // 3) Output projection GEMM
    {
        dim3 grid(CDIM / 128, MROWS / 128);   // (4, 1568)
        sgemm_kernel<2><<<grid, 256>>>(nullptr, w_proj, b_proj, out,
                                       MROWS, CDIM, CDIM);
    }
}

// round 4
// speedup vs baseline: 1.8201x; 1.8201x over previous
#include <cuda_runtime.h>
#include <cuda_fp16.h>
#include <cstdint>
#include <math_constants.h>

// Problem constants
#define CDIM 512
#define NHEAD 16
#define HD 32
#define LTOK 49
#define BNW 4096
#define MROWS (BNW * LTOK)            // 200704
#define NQKV (3 * CDIM)               // 1536
#define SLAB (LTOK * HD)              // 1568
#define WINSTRIDE (NHEAD * SLAB)      // 25088
#define PARTSTRIDE ((size_t)CDIM * MROWS)
#define KDIM 512
#define KITER (KDIM / 16)             // 32 iters of K=16

// Scratch (device globals — no allocation)
__device__ float  g_qkvT[(size_t)NQKV * MROWS];     // qkv channel-major fp32
__device__ __half g_xhi[(size_t)MROWS * CDIM];      // x split hi/lo
__device__ __half g_xlo[(size_t)MROWS * CDIM];
__device__ __half g_ohi[(size_t)MROWS * CDIM];      // attn out split hi/lo
__device__ __half g_olo[(size_t)MROWS * CDIM];
__device__ __half g_whi1[(size_t)NQKV * KDIM];      // w_qkv^T hi/lo [N][K]
__device__ __half g_wlo1[(size_t)NQKV * KDIM];
__device__ __half g_whi2[(size_t)CDIM * KDIM];      // w_proj^T hi/lo
__device__ __half g_wlo2[(size_t)CDIM * KDIM];

// ---------------------------------------------------------------------------
// PTX helpers (sm_80-era ISA — tcgen05 unavailable at compute_103)
// ---------------------------------------------------------------------------
__device__ __forceinline__ uint32_t smem_u32(const void* p) {
    uint32_t a;
    asm("{ .reg .u64 t; cvta.to.shared.u64 t, %1; cvt.u32.u64 %0, t; }"
        : "=r"(a) : "l"(p));
    return a;
}
__device__ __forceinline__ void cp_async16(uint32_t smem, const void* g) {
    asm volatile("cp.async.cg.shared.global [%0], [%1], 16;"
                 :: "r"(smem), "l"(g) : "memory");
}
__device__ __forceinline__ void cp_commit() {
    asm volatile("cp.async.commit_group;" ::: "memory");
}
template <int N>
__device__ __forceinline__ void cp_wait() {
    asm volatile("cp.async.wait_group %0;" :: "n"(N) : "memory");
}
__device__ __forceinline__ void ldsm_x4(uint32_t& r0, uint32_t& r1,
                                        uint32_t& r2, uint32_t& r3,
                                        uint32_t addr) {
    asm volatile("ldmatrix.sync.aligned.m8n8.x4.shared.b16 {%0,%1,%2,%3}, [%4];"
                 : "=r"(r0), "=r"(r1), "=r"(r2), "=r"(r3) : "r"(addr));
}
__device__ __forceinline__ void mma_f16(float* d, const uint32_t* a,
                                        const uint32_t* b) {
    asm volatile(
        "mma.sync.aligned.m16n8k16.row.col.f32.f16.f16.f32 "
        "{%0,%1,%2,%3}, {%4,%5,%6,%7}, {%8,%9}, {%0,%1,%2,%3};"
        : "+f"(d[0]), "+f"(d[1]), "+f"(d[2]), "+f"(d[3])
        : "r"(a[0]), "r"(a[1]), "r"(a[2]), "r"(a[3]), "r"(b[0]), "r"(b[1]));
}

// stage: [Ahi 4K][Alo 4K][Bhi 4K][Blo 4K] = 16KB; rows of 16 fp16 = 32B,
// two 16B chunks per row, XOR swizzle on row bit 2.
#define STAGE_BYTES 16384
#define NSTAGE 4
#define DYN_SMEM 66560   // max(4*16384, 8 warps * 32*65*4 bounce)

__device__ __forceinline__ uint32_t sw16(int row, int c) {
    return (uint32_t)row * 32u + (uint32_t)((c ^ ((row >> 2) & 1)) << 4);
}

// ---------------------------------------------------------------------------
// x -> hi/lo fp16 split (elementwise)
// ---------------------------------------------------------------------------
__global__ __launch_bounds__(256) void split_x_kernel(const float* __restrict__ src) {
    size_t i = ((size_t)blockIdx.x * 256 + threadIdx.x) * 4;
    float4 v = *(const float4*)(src + i);
    __half h0 = __float2half_rn(v.x), h1 = __float2half_rn(v.y);
    __half h2 = __float2half_rn(v.z), h3 = __float2half_rn(v.w);
    __half l0 = __float2half_rn(v.x - __half2float(h0));
    __half l1 = __float2half_rn(v.y - __half2float(h1));
    __half l2 = __float2half_rn(v.z - __half2float(h2));
    __half l3 = __float2half_rn(v.w - __half2float(h3));
    __half2 hh[2] = {__halves2half2(h0, h1), __halves2half2(h2, h3)};
    __half2 ll[2] = {__halves2half2(l0, l1), __halves2half2(l2, l3)};
    *(uint2*)(g_xhi + i) = *(uint2*)hh;
    *(uint2*)(g_xlo + i) = *(uint2*)ll;
}

// ---------------------------------------------------------------------------
// Weight transpose + split: src[k*N + n] -> dst_{hi,lo}[n*K + k]
// ---------------------------------------------------------------------------
template <int SEL>
__global__ void wtrans_kernel(const float* __restrict__ src, int K, int N) {
    __half* dhi = (SEL == 1) ? g_whi1 : g_whi2;
    __half* dlo = (SEL == 1) ? g_wlo1 : g_wlo2;
    __shared__ float t[32][33];
    int n0 = blockIdx.x * 32, k0 = blockIdx.y * 32;
    int x = threadIdx.x, y = threadIdx.y;
    #pragma unroll
    for (int i = y; i < 32; i += 8)
        t[i][x] = src[(size_t)(k0 + i) * N + n0 + x];
    __syncthreads();
    #pragma unroll
    for (int i = y; i < 32; i += 8) {
        float v = t[x][i];
        __half h = __float2half_rn(v);
        __half l = __float2half_rn(v - __half2float(h));
        dhi[(size_t)(n0 + i) * K + k0 + x] = h;
        dlo[(size_t)(n0 + i) * K + k0 + x] = l;
    }
}

// ---------------------------------------------------------------------------
// fp16x3 mma.sync GEMM: C[M,N] = A @ B^T + bias  (A=Ahi+Alo, B=Bhi+Blo)
// MODE 1: A = x split, B = wqkv split, scatter epilogue g_qkvT[col*MROWS+row]
// MODE 2: A = attnout split, B = wproj split, row-major epilogue to C
// 128x128x16 tile, 256 threads, warp tile 64x32, 4-stage cp.async.
// ---------------------------------------------------------------------------
template <int MODE>
__global__ __launch_bounds__(256) void gemm_f16x3(
    const float* __restrict__ bias, float* __restrict__ C, int N)
{
    extern __shared__ char smem[];
    const __half* Ahi = (MODE == 1) ? g_xhi : g_ohi;
    const __half* Alo = (MODE == 1) ? g_xlo : g_olo;
    const __half* Bhi = (MODE == 1) ? g_whi1 : g_whi2;
    const __half* Blo = (MODE == 1) ? g_wlo1 : g_wlo2;

    const int tid = threadIdx.x;
    const int lane = tid & 31, wid = tid >> 5;
    const int warpM = wid & 1, warpN = wid >> 1;   // 2 x 4 warps
    const int bm = blockIdx.y, bn = blockIdx.x;
    const uint32_t sbase = smem_u32(smem);

    // loader mapping: 256 chunks (128 rows x 2) per plane, one per thread
    const int grow = tid >> 1, gch = tid & 1;
    const uint32_t soff = sw16(grow, gch);
    const __half* gAhi = Ahi + (size_t)(bm * 128 + grow) * KDIM + gch * 8;
    const __half* gAlo = Alo + (size_t)(bm * 128 + grow) * KDIM + gch * 8;
    const __half* gBhi = Bhi + (size_t)(bn * 128 + grow) * KDIM + gch * 8;
    const __half* gBlo = Blo + (size_t)(bn * 128 + grow) * KDIM + gch * 8;

    float acc[4][4][4];
    #pragma unroll
    for (int i = 0; i < 4; i++)
        #pragma unroll
        for (int j = 0; j < 4; j++)
            #pragma unroll
            for (int q = 0; q < 4; q++) acc[i][j][q] = 0.f;

    // prologue: 3 stages in flight
    #pragma unroll
    for (int s = 0; s < NSTAGE - 1; s++) {
        uint32_t st = sbase + s * STAGE_BYTES;
        int k0 = s * 16;
        cp_async16(st + soff,          gAhi + k0);
        cp_async16(st + 4096 + soff,   gAlo + k0);
        cp_async16(st + 8192 + soff,   gBhi + k0);
        cp_async16(st + 12288 + soff,  gBlo + k0);
        cp_commit();
    }

    // ldmatrix offsets (per warp)
    const int lrow = lane & 15, lhalf = lane >> 4;
    uint32_t offA[4], offB[2];
    #pragma unroll
    for (int mt = 0; mt < 4; mt++)
        offA[mt] = sw16(warpM * 64 + mt * 16 + lrow, lhalf);
    #pragma unroll
    for (int nt2 = 0; nt2 < 2; nt2++)
        offB[nt2] = sw16(warpN * 32 + nt2 * 16 + lrow, lhalf);

    for (int it = 0; it < KITER; it++) {
        cp_wait<NSTAGE - 2>();
        __syncthreads();

        if (it + NSTAGE - 1 < KITER) {
            int s = (it + NSTAGE - 1) % NSTAGE;
            uint32_t st = sbase + s * STAGE_BYTES;
            int k0 = (it + NSTAGE - 1) * 16;
            cp_async16(st + soff,         gAhi + k0);
            cp_async16(st + 4096 + soff,  gAlo + k0);
            cp_async16(st + 8192 + soff,  gBhi + k0);
            cp_async16(st + 12288 + soff, gBlo + k0);
        }
        cp_commit();

        const uint32_t st = sbase + (it % NSTAGE) * STAGE_BYTES;

        uint32_t ah[4][4], al[4][4], bh[4][2], bl[4][2];
        #pragma unroll
        for (int mt = 0; mt < 4; mt++) {
            ldsm_x4(ah[mt][0], ah[mt][1], ah[mt][2], ah[mt][3], st + offA[mt]);
            ldsm_x4(al[mt][0], al[mt][1], al[mt][2], al[mt][3], st + 4096 + offA[mt]);
        }
        #pragma unroll
        for (int nt2 = 0; nt2 < 2; nt2++) {
            uint32_t r0, r1, r2, r3;
            ldsm_x4(r0, r1, r2, r3, st + 8192 + offB[nt2]);
            bh[nt2 * 2 + 0][0] = r0; bh[nt2 * 2 + 0][1] = r2;
            bh[nt2 * 2 + 1][0] = r1; bh[nt2 * 2 + 1][1] = r3;
            ldsm_x4(r0, r1, r2, r3, st + 12288 + offB[nt2]);
            bl[nt2 * 2 + 0][0] = r0; bl[nt2 * 2 + 0][1] = r2;
            bl[nt2 * 2 + 1][0] = r1; bl[nt2 * 2 + 1][1] = r3;
        }
        #pragma unroll
        for (int mt = 0; mt < 4; mt++)
            #pragma unroll
            for (int nt = 0; nt < 4; nt++) {
                mma_f16(acc[mt][nt], ah[mt], bh[nt]);
                mma_f16(acc[mt][nt], ah[mt], bl[nt]);
                mma_f16(acc[mt][nt], al[mt], bh[nt]);
            }
    }

    cp_wait<0>();
    __syncthreads();   // before smem reuse as bounce

    if (MODE == 2) {
        #pragma unroll
        for (int mt = 0; mt < 4; mt++) {
            #pragma unroll
            for (int nt = 0; nt < 4; nt++) {
                int m0 = bm * 128 + warpM * 64 + mt * 16 + (lane >> 2);
                int n0 = bn * 128 + warpN * 32 + nt * 8 + (lane & 3) * 2;
                float2 bv = *(const float2*)(bias + n0);
                float2 v0 = make_float2(acc[mt][nt][0] + bv.x, acc[mt][nt][1] + bv.y);
                float2 v1 = make_float2(acc[mt][nt][2] + bv.x, acc[mt][nt][3] + bv.y);
                *(float2*)(C + (size_t)m0 * N + n0) = v0;
                *(float2*)(C + (size_t)(m0 + 8) * N + n0) = v1;
            }
        }
    } else {
        float* bounce = (float*)smem + wid * (32 * 65);
        #pragma unroll
        for (int mt = 0; mt < 4; mt++) {
            #pragma unroll
            for (int nt = 0; nt < 4; nt++) {
                int nl = nt * 8 + (lane & 3) * 2;
                int ml = mt * 16 + (lane >> 2);
                bounce[nl * 65 + ml]            = acc[mt][nt][0];
                bounce[(nl + 1) * 65 + ml]      = acc[mt][nt][1];
                bounce[nl * 65 + ml + 8]        = acc[mt][nt][2];
                bounce[(nl + 1) * 65 + ml + 8]  = acc[mt][nt][3];
            }
        }
        __syncwarp();
        int col = bn * 128 + warpN * 32 + lane;
        float bv = bias[col];
        float* dst = g_qkvT + (size_t)col * MROWS + bm * 128 + warpM * 64;
        const float* src = bounce + lane * 65;
        #pragma unroll
        for (int q = 0; q < 16; q++) {
            float4 v;
            v.x = src[q * 4 + 0] + bv;
            v.y = src[q * 4 + 1] + bv;
            v.z = src[q * 4 + 2] + bv;
            v.w = src[q * 4 + 3] + bv;
            ((float4*)dst)[q] = v;
        }
    }
}

// ---------------------------------------------------------------------------
// Attention: one block per (window, head); writes hi/lo fp16 split output
// ---------------------------------------------------------------------------
__global__ __launch_bounds__(256) void attn_kernel(
    const float* __restrict__ mask,
    const float* __restrict__ bias_table,
    const int*   __restrict__ index_table)
{
    __shared__ float sQ[SLAB];
    __shared__ float sKT[HD * LTOK];
    __shared__ float sV[SLAB];
    __shared__ float sS[LTOK * LTOK];

    int tid = threadIdx.x;
    int b2 = blockIdx.x >> 4;
    int h  = blockIdx.x & 15;

    size_t base = (size_t)b2 * WINSTRIDE + (size_t)h * SLAB;
    const float* Qg = g_qkvT + base;
    const float* Kg = g_qkvT + PARTSTRIDE + base;
    const float* Vg = g_qkvT + 2 * PARTSTRIDE + base;

    for (int t = tid; t < SLAB / 4; t += 256) {
        ((float4*)sQ)[t] = ((const float4*)Qg)[t];
        ((float4*)sV)[t] = ((const float4*)Vg)[t];
        float4 kv = ((const float4*)Kg)[t];
        int j  = t * 4;
        int l2 = j >> 5;
        int d  = j & 31;
        sKT[(d + 0) * LTOK + l2] = kv.x;
        sKT[(d + 1) * LTOK + l2] = kv.y;
        sKT[(d + 2) * LTOK + l2] = kv.z;
        sKT[(d + 3) * LTOK + l2] = kv.w;
    }
    __syncthreads();

    const float* mrow = mask + (size_t)(b2 & 63) * (LTOK * LTOK);
    for (int o = tid; o < LTOK * LTOK; o += 256) {
        int l = o / LTOK;
        int m = o - l * LTOK;
        float acc = 0.f;
        #pragma unroll
        for (int d = 0; d < HD; d++)
            acc = fmaf(sQ[l * HD + d], sKT[d * LTOK + m], acc);
        int idx = index_table[o];
        sS[o] = acc + bias_table[idx * NHEAD + h] + mrow[o];
    }
    __syncthreads();

    int warp = tid >> 5, lane = tid & 31;
    for (int row = warp; row < LTOK; row += 8) {
        float* s = sS + row * LTOK;
        float e0 = s[lane];
        float e1 = (lane + 32 < LTOK) ? s[lane + 32] : -CUDART_INF_F;
        float mx = fmaxf(e0, e1);
        #pragma unroll
        for (int off = 16; off; off >>= 1)
            mx = fmaxf(mx, __shfl_xor_sync(0xffffffffu, mx, off));
        float p0 = __expf(e0 - mx);
        float p1 = (lane + 32 < LTOK) ? __expf(e1 - mx) : 0.f;
        float sum = p0 + p1;
        #pragma unroll
        for (int off = 16; off; off >>= 1)
            sum += __shfl_xor_sync(0xffffffffu, sum, off);
        float inv = 1.f / sum;
        s[lane] = p0 * inv;
        if (lane + 32 < LTOK) s[lane + 32] = p1 * inv;
    }
    __syncthreads();

    for (int o = tid; o < SLAB; o += 256) {
        int l = o >> 5;
        int d = o & 31;
        const float* p = sS + l * LTOK;
        float acc = 0.f;
        #pragma unroll
        for (int m = 0; m < LTOK; m++)
            acc = fmaf(p[m], sV[m * HD + d], acc);
        __half hv = __float2half_rn(acc);
        __half lv = __float2half_rn(acc - __half2float(hv));
        size_t oidx = ((size_t)b2 * LTOK + l) * CDIM + h * HD + d;
        g_ohi[oidx] = hv;
        g_olo[oidx] = lv;
    }
}

// ---------------------------------------------------------------------------
extern "C" void kernel_launch(void* const* d_in, const int* in_sizes, int n_in,
                              void* d_out, int out_size)
{
    const float* x           = (const float*)d_in[0];
    const float* mask        = (const float*)d_in[1];
    const float* w_qkv       = (const float*)d_in[2];
    const float* b_qkv       = (const float*)d_in[3];
    const float* w_proj      = (const float*)d_in[4];
    const float* b_proj      = (const float*)d_in[5];
    const float* bias_table  = (const float*)d_in[6];
    const int*   index_table = (const int*)d_in[7];
    float* out = (float*)d_out;

    cudaFuncSetAttribute(gemm_f16x3<1>, cudaFuncAttributeMaxDynamicSharedMemorySize, DYN_SMEM);
    cudaFuncSetAttribute(gemm_f16x3<2>, cudaFuncAttributeMaxDynamicSharedMemorySize, DYN_SMEM);

    // 0) weight transpose+split and x split
    wtrans_kernel<1><<<dim3(NQKV / 32, KDIM / 32), dim3(32, 8)>>>(w_qkv, KDIM, NQKV);
    wtrans_kernel<2><<<dim3(CDIM / 32, KDIM / 32), dim3(32, 8)>>>(w_proj, KDIM, CDIM);
    split_x_kernel<<<((size_t)MROWS * CDIM) / 4 / 256, 256>>>(x);

    // 1) QKV GEMM (fp16x3) with channel-major scatter epilogue
    gemm_f16x3<1><<<dim3(NQKV / 128, MROWS / 128), 256, DYN_SMEM>>>(b_qkv, nullptr, NQKV);

    // 2) fused window attention
    attn_kernel<<<BNW * NHEAD, 256>>>(mask, bias_table, index_table);

    // 3) projection GEMM (fp16x3)
    gemm_f16x3<2><<<dim3(CDIM / 128, MROWS / 128), 256, DYN_SMEM>>>(b_proj, out, CDIM);
}

// round 5
// speedup vs baseline: 2.0797x; 1.1427x over previous
#include <cuda_runtime.h>
#include <cuda_fp16.h>
#include <cstdint>
#include <math_constants.h>

// Problem constants
#define CDIM 512
#define NHEAD 16
#define HD 32
#define LTOK 49
#define BNW 4096
#define MROWS (BNW * LTOK)            // 200704
#define NQKV (3 * CDIM)               // 1536
#define SLAB (LTOK * HD)              // 1568
#define WINSTRIDE (NHEAD * SLAB)      // 25088
#define PARTSTRIDE ((size_t)CDIM * MROWS)
#define KDIM 512
#define KITER (KDIM / 16)             // 32 iters of K=16
#define LP 52                          // padded token dim

// Scratch (device globals — no allocation)
__device__ float  g_qkvT[(size_t)NQKV * MROWS];     // qkv channel-major fp32
__device__ __half g_xhi[(size_t)MROWS * CDIM];      // x split hi/lo
__device__ __half g_xlo[(size_t)MROWS * CDIM];
__device__ __half g_ohi[(size_t)MROWS * CDIM];      // attn out split hi/lo
__device__ __half g_olo[(size_t)MROWS * CDIM];
__device__ __half g_whi1[(size_t)NQKV * KDIM];      // w_qkv^T hi/lo [N][K]
__device__ __half g_wlo1[(size_t)NQKV * KDIM];
__device__ __half g_whi2[(size_t)CDIM * KDIM];      // w_proj^T hi/lo
__device__ __half g_wlo2[(size_t)CDIM * KDIM];

// ---------------------------------------------------------------------------
// PTX helpers (sm_80-era ISA — tcgen05 unavailable at compute_103)
// ---------------------------------------------------------------------------
__device__ __forceinline__ uint32_t smem_u32(const void* p) {
    uint32_t a;
    asm("{ .reg .u64 t; cvta.to.shared.u64 t, %1; cvt.u32.u64 %0, t; }"
        : "=r"(a) : "l"(p));
    return a;
}
__device__ __forceinline__ void cp_async16(uint32_t smem, const void* g) {
    asm volatile("cp.async.cg.shared.global [%0], [%1], 16;"
                 :: "r"(smem), "l"(g) : "memory");
}
__device__ __forceinline__ void cp_commit() {
    asm volatile("cp.async.commit_group;" ::: "memory");
}
template <int N>
__device__ __forceinline__ void cp_wait() {
    asm volatile("cp.async.wait_group %0;" :: "n"(N) : "memory");
}
__device__ __forceinline__ void ldsm_x4(uint32_t& r0, uint32_t& r1,
                                        uint32_t& r2, uint32_t& r3,
                                        uint32_t addr) {
    asm volatile("ldmatrix.sync.aligned.m8n8.x4.shared.b16 {%0,%1,%2,%3}, [%4];"
                 : "=r"(r0), "=r"(r1), "=r"(r2), "=r"(r3) : "r"(addr));
}
__device__ __forceinline__ void mma_f16(float* d, const uint32_t* a,
                                        const uint32_t* b) {
    asm volatile(
        "mma.sync.aligned.m16n8k16.row.col.f32.f16.f16.f32 "
        "{%0,%1,%2,%3}, {%4,%5,%6,%7}, {%8,%9}, {%0,%1,%2,%3};"
        : "+f"(d[0]), "+f"(d[1]), "+f"(d[2]), "+f"(d[3])
        : "r"(a[0]), "r"(a[1]), "r"(a[2]), "r"(a[3]), "r"(b[0]), "r"(b[1]));
}

#define STAGE_BYTES 16384
#define NSTAGE 4
#define DYN_SMEM 66560   // max(4*16384, 8 warps * 32*65*4 bounce)

__device__ __forceinline__ uint32_t sw16(int row, int c) {
    return (uint32_t)row * 32u + (uint32_t)((c ^ ((row >> 2) & 1)) << 4);
}

// ---------------------------------------------------------------------------
// x -> hi/lo fp16 split (elementwise)
// ---------------------------------------------------------------------------
__global__ __launch_bounds__(256) void split_x_kernel(const float* __restrict__ src) {
    size_t i = ((size_t)blockIdx.x * 256 + threadIdx.x) * 4;
    float4 v = *(const float4*)(src + i);
    __half h0 = __float2half_rn(v.x), h1 = __float2half_rn(v.y);
    __half h2 = __float2half_rn(v.z), h3 = __float2half_rn(v.w);
    __half l0 = __float2half_rn(v.x - __half2float(h0));
    __half l1 = __float2half_rn(v.y - __half2float(h1));
    __half l2 = __float2half_rn(v.z - __half2float(h2));
    __half l3 = __float2half_rn(v.w - __half2float(h3));
    __half2 hh[2] = {__halves2half2(h0, h1), __halves2half2(h2, h3)};
    __half2 ll[2] = {__halves2half2(l0, l1), __halves2half2(l2, l3)};
    *(uint2*)(g_xhi + i) = *(uint2*)hh;
    *(uint2*)(g_xlo + i) = *(uint2*)ll;
}

// ---------------------------------------------------------------------------
// Weight transpose + split: src[k*N + n] -> dst_{hi,lo}[n*K + k]
// ---------------------------------------------------------------------------
template <int SEL>
__global__ void wtrans_kernel(const float* __restrict__ src, int K, int N) {
    __half* dhi = (SEL == 1) ? g_whi1 : g_whi2;
    __half* dlo = (SEL == 1) ? g_wlo1 : g_wlo2;
    __shared__ float t[32][33];
    int n0 = blockIdx.x * 32, k0 = blockIdx.y * 32;
    int x = threadIdx.x, y = threadIdx.y;
    #pragma unroll
    for (int i = y; i < 32; i += 8)
        t[i][x] = src[(size_t)(k0 + i) * N + n0 + x];
    __syncthreads();
    #pragma unroll
    for (int i = y; i < 32; i += 8) {
        float v = t[x][i];
        __half h = __float2half_rn(v);
        __half l = __float2half_rn(v - __half2float(h));
        dhi[(size_t)(n0 + i) * K + k0 + x] = h;
        dlo[(size_t)(n0 + i) * K + k0 + x] = l;
    }
}

// ---------------------------------------------------------------------------
// fp16x3 mma.sync GEMM (unchanged from R4 — passing, tensor 46.7%)
// ---------------------------------------------------------------------------
template <int MODE>
__global__ __launch_bounds__(256) void gemm_f16x3(
    const float* __restrict__ bias, float* __restrict__ C, int N)
{
    extern __shared__ char smem[];
    const __half* Ahi = (MODE == 1) ? g_xhi : g_ohi;
    const __half* Alo = (MODE == 1) ? g_xlo : g_olo;
    const __half* Bhi = (MODE == 1) ? g_whi1 : g_whi2;
    const __half* Blo = (MODE == 1) ? g_wlo1 : g_wlo2;

    const int tid = threadIdx.x;
    const int lane = tid & 31, wid = tid >> 5;
    const int warpM = wid & 1, warpN = wid >> 1;
    const int bm = blockIdx.y, bn = blockIdx.x;
    const uint32_t sbase = smem_u32(smem);

    const int grow = tid >> 1, gch = tid & 1;
    const uint32_t soff = sw16(grow, gch);
    const __half* gAhi = Ahi + (size_t)(bm * 128 + grow) * KDIM + gch * 8;
    const __half* gAlo = Alo + (size_t)(bm * 128 + grow) * KDIM + gch * 8;
    const __half* gBhi = Bhi + (size_t)(bn * 128 + grow) * KDIM + gch * 8;
    const __half* gBlo = Blo + (size_t)(bn * 128 + grow) * KDIM + gch * 8;

    float acc[4][4][4];
    #pragma unroll
    for (int i = 0; i < 4; i++)
        #pragma unroll
        for (int j = 0; j < 4; j++)
            #pragma unroll
            for (int q = 0; q < 4; q++) acc[i][j][q] = 0.f;

    #pragma unroll
    for (int s = 0; s < NSTAGE - 1; s++) {
        uint32_t st = sbase + s * STAGE_BYTES;
        int k0 = s * 16;
        cp_async16(st + soff,          gAhi + k0);
        cp_async16(st + 4096 + soff,   gAlo + k0);
        cp_async16(st + 8192 + soff,   gBhi + k0);
        cp_async16(st + 12288 + soff,  gBlo + k0);
        cp_commit();
    }

    const int lrow = lane & 15, lhalf = lane >> 4;
    uint32_t offA[4], offB[2];
    #pragma unroll
    for (int mt = 0; mt < 4; mt++)
        offA[mt] = sw16(warpM * 64 + mt * 16 + lrow, lhalf);
    #pragma unroll
    for (int nt2 = 0; nt2 < 2; nt2++)
        offB[nt2] = sw16(warpN * 32 + nt2 * 16 + lrow, lhalf);

    for (int it = 0; it < KITER; it++) {
        cp_wait<NSTAGE - 2>();
        __syncthreads();

        if (it + NSTAGE - 1 < KITER) {
            int s = (it + NSTAGE - 1) % NSTAGE;
            uint32_t st = sbase + s * STAGE_BYTES;
            int k0 = (it + NSTAGE - 1) * 16;
            cp_async16(st + soff,         gAhi + k0);
            cp_async16(st + 4096 + soff,  gAlo + k0);
            cp_async16(st + 8192 + soff,  gBhi + k0);
            cp_async16(st + 12288 + soff, gBlo + k0);
        }
        cp_commit();

        const uint32_t st = sbase + (it % NSTAGE) * STAGE_BYTES;

        uint32_t ah[4][4], al[4][4], bh[4][2], bl[4][2];
        #pragma unroll
        for (int mt = 0; mt < 4; mt++) {
            ldsm_x4(ah[mt][0], ah[mt][1], ah[mt][2], ah[mt][3], st + offA[mt]);
            ldsm_x4(al[mt][0], al[mt][1], al[mt][2], al[mt][3], st + 4096 + offA[mt]);
        }
        #pragma unroll
        for (int nt2 = 0; nt2 < 2; nt2++) {
            uint32_t r0, r1, r2, r3;
            ldsm_x4(r0, r1, r2, r3, st + 8192 + offB[nt2]);
            bh[nt2 * 2 + 0][0] = r0; bh[nt2 * 2 + 0][1] = r2;
            bh[nt2 * 2 + 1][0] = r1; bh[nt2 * 2 + 1][1] = r3;
            ldsm_x4(r0, r1, r2, r3, st + 12288 + offB[nt2]);
            bl[nt2 * 2 + 0][0] = r0; bl[nt2 * 2 + 0][1] = r2;
            bl[nt2 * 2 + 1][0] = r1; bl[nt2 * 2 + 1][1] = r3;
        }
        #pragma unroll
        for (int mt = 0; mt < 4; mt++)
            #pragma unroll
            for (int nt = 0; nt < 4; nt++) {
                mma_f16(acc[mt][nt], ah[mt], bh[nt]);
                mma_f16(acc[mt][nt], ah[mt], bl[nt]);
                mma_f16(acc[mt][nt], al[mt], bh[nt]);
            }
    }

    cp_wait<0>();
    __syncthreads();

    if (MODE == 2) {
        #pragma unroll
        for (int mt = 0; mt < 4; mt++) {
            #pragma unroll
            for (int nt = 0; nt < 4; nt++) {
                int m0 = bm * 128 + warpM * 64 + mt * 16 + (lane >> 2);
                int n0 = bn * 128 + warpN * 32 + nt * 8 + (lane & 3) * 2;
                float2 bv = *(const float2*)(bias + n0);
                float2 v0 = make_float2(acc[mt][nt][0] + bv.x, acc[mt][nt][1] + bv.y);
                float2 v1 = make_float2(acc[mt][nt][2] + bv.x, acc[mt][nt][3] + bv.y);
                *(float2*)(C + (size_t)m0 * N + n0) = v0;
                *(float2*)(C + (size_t)(m0 + 8) * N + n0) = v1;
            }
        }
    } else {
        float* bounce = (float*)smem + wid * (32 * 65);
        #pragma unroll
        for (int mt = 0; mt < 4; mt++) {
            #pragma unroll
            for (int nt = 0; nt < 4; nt++) {
                int nl = nt * 8 + (lane & 3) * 2;
                int ml = mt * 16 + (lane >> 2);
                bounce[nl * 65 + ml]            = acc[mt][nt][0];
                bounce[(nl + 1) * 65 + ml]      = acc[mt][nt][1];
                bounce[nl * 65 + ml + 8]        = acc[mt][nt][2];
                bounce[(nl + 1) * 65 + ml + 8]  = acc[mt][nt][3];
            }
        }
        __syncwarp();
        int col = bn * 128 + warpN * 32 + lane;
        float bv = bias[col];
        float* dst = g_qkvT + (size_t)col * MROWS + bm * 128 + warpM * 64;
        const float* src = bounce + lane * 65;
        #pragma unroll
        for (int q = 0; q < 16; q++) {
            float4 v;
            v.x = src[q * 4 + 0] + bv;
            v.y = src[q * 4 + 1] + bv;
            v.z = src[q * 4 + 2] + bv;
            v.w = src[q * 4 + 3] + bv;
            ((float4*)dst)[q] = v;
        }
    }
}

// ---------------------------------------------------------------------------
// Attention (register-tiled): one block per (window, head).
// QT/KT stored [d][l] padded to LP=52 -> float4 reads in 4x4 score tiles.
// PV: 4x4 tiles, broadcast p + float4 V rows (conflict-free).
// ---------------------------------------------------------------------------
__global__ __launch_bounds__(256) void attn_kernel(
    const float* __restrict__ mask,
    const float* __restrict__ bias_table,
    const int*   __restrict__ index_table)
{
    __shared__ float sQT[HD * LP];       // [d][l]
    __shared__ float sKT[HD * LP];       // [d][m]
    __shared__ float sV[LTOK * HD];      // [m][d]
    __shared__ float sS[LP * LP];        // scores, row stride LP

    int tid = threadIdx.x;
    int b2 = blockIdx.x >> 4;
    int h  = blockIdx.x & 15;

    size_t base = (size_t)b2 * WINSTRIDE + (size_t)h * SLAB;
    const float* Qg = g_qkvT + base;
    const float* Kg = g_qkvT + PARTSTRIDE + base;
    const float* Vg = g_qkvT + 2 * PARTSTRIDE + base;

    // Load slabs; Q and K transposed to [d][l]
    for (int t = tid; t < SLAB / 4; t += 256) {
        float4 qv = ((const float4*)Qg)[t];
        float4 kv = ((const float4*)Kg)[t];
        ((float4*)sV)[t] = ((const float4*)Vg)[t];
        int j  = t * 4;
        int l2 = j >> 5;
        int d  = j & 31;
        sQT[(d + 0) * LP + l2] = qv.x;
        sQT[(d + 1) * LP + l2] = qv.y;
        sQT[(d + 2) * LP + l2] = qv.z;
        sQT[(d + 3) * LP + l2] = qv.w;
        sKT[(d + 0) * LP + l2] = kv.x;
        sKT[(d + 1) * LP + l2] = kv.y;
        sKT[(d + 2) * LP + l2] = kv.z;
        sKT[(d + 3) * LP + l2] = kv.w;
    }
    __syncthreads();

    // Scores: 13x13 grid of 4x4 tiles (169 units). Padded lanes read garbage
    // smem beyond l,m=48 but those acc entries are never stored.
    const float* mrow = mask + (size_t)(b2 & 63) * (LTOK * LTOK);
    if (tid < 169) {
        int lt = tid / 13, mt = tid - lt * 13;
        int l0 = lt * 4, m0 = mt * 4;
        float acc[4][4];
        #pragma unroll
        for (int i = 0; i < 4; i++)
            #pragma unroll
            for (int j = 0; j < 4; j++) acc[i][j] = 0.f;
        #pragma unroll
        for (int d = 0; d < HD; d++) {
            float4 q = *(const float4*)&sQT[d * LP + l0];
            float4 k = *(const float4*)&sKT[d * LP + m0];
            float qa[4] = {q.x, q.y, q.z, q.w};
            float ka[4] = {k.x, k.y, k.z, k.w};
            #pragma unroll
            for (int i = 0; i < 4; i++)
                #pragma unroll
                for (int j = 0; j < 4; j++)
                    acc[i][j] = fmaf(qa[i], ka[j], acc[i][j]);
        }
        #pragma unroll
        for (int i = 0; i < 4; i++) {
            int l = l0 + i;
            if (l < LTOK) {
                #pragma unroll
                for (int j = 0; j < 4; j++) {
                    int m = m0 + j;
                    if (m < LTOK) {
                        int o = l * LTOK + m;
                        sS[l * LP + m] = acc[i][j]
                            + bias_table[index_table[o] * NHEAD + h] + mrow[o];
                    }
                }
            }
        }
    }
    __syncthreads();

    // Softmax per row (warp per row)
    int warp = tid >> 5, lane = tid & 31;
    for (int row = warp; row < LTOK; row += 8) {
        float* s = sS + row * LP;
        float e0 = s[lane];
        float e1 = (lane + 32 < LTOK) ? s[lane + 32] : -CUDART_INF_F;
        float mx = fmaxf(e0, e1);
        #pragma unroll
        for (int off = 16; off; off >>= 1)
            mx = fmaxf(mx, __shfl_xor_sync(0xffffffffu, mx, off));
        float p0 = __expf(e0 - mx);
        float p1 = (lane + 32 < LTOK) ? __expf(e1 - mx) : 0.f;
        float sum = p0 + p1;
        #pragma unroll
        for (int off = 16; off; off >>= 1)
            sum += __shfl_xor_sync(0xffffffffu, sum, off);
        float inv = 1.f / sum;
        s[lane] = p0 * inv;
        if (lane + 32 < LTOK) s[lane + 32] = p1 * inv;
    }
    __syncthreads();

    // PV: 13(l) x 8(d) grid of 4x4 tiles (104 units)
    if (tid < 104) {
        int dt = tid & 7, lt = tid >> 3;
        int l0 = lt * 4, d0 = dt * 4;
        float acc[4][4];
        #pragma unroll
        for (int i = 0; i < 4; i++)
            #pragma unroll
            for (int j = 0; j < 4; j++) acc[i][j] = 0.f;
        for (int m = 0; m < LTOK; m++) {
            float4 v = *(const float4*)&sV[m * HD + d0];
            float va[4] = {v.x, v.y, v.z, v.w};
            float p0 = sS[(l0 + 0) * LP + m];
            float p1 = sS[(l0 + 1) * LP + m];
            float p2 = sS[(l0 + 2) * LP + m];
            float p3 = sS[(l0 + 3) * LP + m];
            #pragma unroll
            for (int j = 0; j < 4; j++) {
                acc[0][j] = fmaf(p0, va[j], acc[0][j]);
                acc[1][j] = fmaf(p1, va[j], acc[1][j]);
                acc[2][j] = fmaf(p2, va[j], acc[2][j]);
                acc[3][j] = fmaf(p3, va[j], acc[3][j]);
            }
        }
        #pragma unroll
        for (int i = 0; i < 4; i++) {
            int l = l0 + i;
            if (l < LTOK) {
                size_t oidx = ((size_t)b2 * LTOK + l) * CDIM + h * HD + d0;
                __half hv[4], lv[4];
                #pragma unroll
                for (int j = 0; j < 4; j++) {
                    hv[j] = __float2half_rn(acc[i][j]);
                    lv[j] = __float2half_rn(acc[i][j] - __half2float(hv[j]));
                }
                *(uint2*)(g_ohi + oidx) = *(uint2*)hv;
                *(uint2*)(g_olo + oidx) = *(uint2*)lv;
            }
        }
    }
}

// ---------------------------------------------------------------------------
extern "C" void kernel_launch(void* const* d_in, const int* in_sizes, int n_in,
                              void* d_out, int out_size)
{
    const float* x           = (const float*)d_in[0];
    const float* mask        = (const float*)d_in[1];
    const float* w_qkv       = (const float*)d_in[2];
    const float* b_qkv       = (const float*)d_in[3];
    const float* w_proj      = (const float*)d_in[4];
    const float* b_proj      = (const float*)d_in[5];
    const float* bias_table  = (const float*)d_in[6];
    const int*   index_table = (const int*)d_in[7];
    float* out = (float*)d_out;

    cudaFuncSetAttribute(gemm_f16x3<1>, cudaFuncAttributeMaxDynamicSharedMemorySize, DYN_SMEM);
    cudaFuncSetAttribute(gemm_f16x3<2>, cudaFuncAttributeMaxDynamicSharedMemorySize, DYN_SMEM);

    // 0) weight transpose+split and x split
    wtrans_kernel<1><<<dim3(NQKV / 32, KDIM / 32), dim3(32, 8)>>>(w_qkv, KDIM, NQKV);
    wtrans_kernel<2><<<dim3(CDIM / 32, KDIM / 32), dim3(32, 8)>>>(w_proj, KDIM, CDIM);
    split_x_kernel<<<((size_t)MROWS * CDIM) / 4 / 256, 256>>>(x);

    // 1) QKV GEMM (fp16x3) with channel-major scatter epilogue
    gemm_f16x3<1><<<dim3(NQKV / 128, MROWS / 128), 256, DYN_SMEM>>>(b_qkv, nullptr, NQKV);

    // 2) fused window attention (register-tiled)
    attn_kernel<<<BNW * NHEAD, 256>>>(mask, bias_table, index_table);

    // 3) projection GEMM (fp16x3)
    gemm_f16x3<2><<<dim3(CDIM / 128, MROWS / 128), 256, DYN_SMEM>>>(b_proj, out, CDIM);
}